// round 1
// baseline (speedup 1.0000x reference)
#include <cuda_runtime.h>
#include <cuda_bf16.h>

#define Nn  50000
#define Ee  640000
#define HIDd 128
#define Hh  8
#define Cc  16
#define EFd 16
#define Ll  3

// ---------------- scratch (static device globals; no allocations) ----------------
__device__ __align__(16) float g_xl[Nn * HIDd];
__device__ __align__(16) float g_xr[Nn * HIDd];
__device__ __align__(16) float g_num[Nn * HIDd];
__device__ __align__(16) float g_den[Nn * Hh];
__device__ __align__(16) float g_M[Ll * EFd * HIDd];
__device__ __align__(16) float g_c[Ll * HIDd];

// ---------------- small utility kernels ----------------
__global__ void copy_kernel(const float4* __restrict__ src, float4* __restrict__ dst, int n4) {
    int i = blockIdx.x * blockDim.x + threadIdx.x;
    if (i < n4) dst[i] = src[i];
}

__global__ void zero_kernel(float4* __restrict__ num, float4* __restrict__ den,
                            int n4num, int n4den) {
    int i = blockIdx.x * blockDim.x + threadIdx.x;
    float4 z = make_float4(0.f, 0.f, 0.f, 0.f);
    if (i < n4num) num[i] = z;
    if (i < n4den) den[i] = z;
}

// M[l] = Wt(16x128) @ We[l](128x128); c[l] = bt @ We[l]
__global__ void precompute_kernel(const float* __restrict__ Wt, const float* __restrict__ bt,
                                  const float* __restrict__ We,
                                  float* __restrict__ M, float* __restrict__ cv) {
    int l = blockIdx.x;
    int j = threadIdx.x;  // 0..127
    const float* Wel = We + l * HIDd * HIDd;
    float acc[EFd];
#pragma unroll
    for (int k = 0; k < EFd; k++) acc[k] = 0.f;
    float cacc = 0.f;
    for (int i = 0; i < HIDd; i++) {
        float w = Wel[i * HIDd + j];
        cacc = fmaf(bt[i], w, cacc);
#pragma unroll
        for (int k = 0; k < EFd; k++) acc[k] = fmaf(Wt[k * HIDd + i], w, acc[k]);
    }
#pragma unroll
    for (int k = 0; k < EFd; k++) M[l * EFd * HIDd + k * HIDd + j] = acc[k];
    cv[l * HIDd + j] = cacc;
}

// ---------------- SGEMM: C[nrows,128] = A[nrows,128] @ W[128,128] + bias ----------------
__global__ void __launch_bounds__(256, 2) gemm128(const float* __restrict__ A,
                                                  const float* __restrict__ W,
                                                  const float* __restrict__ bias,
                                                  float* __restrict__ C, int nrows) {
    __shared__ __align__(16) float As[32][132];
    __shared__ __align__(16) float Bs[32][128];
    const int tid = threadIdx.x;
    const int tn = (tid & 15) * 8;   // output col base
    const int tm = (tid >> 4) * 8;   // output row base within tile
    const int rowBase = blockIdx.x * 128;

    float acc[8][8];
#pragma unroll
    for (int i = 0; i < 8; i++)
#pragma unroll
        for (int j = 0; j < 8; j++) acc[i][j] = 0.f;

    const int ar = tid >> 3;         // 0..31
    const int ak = (tid & 7) << 2;   // 0,4,..,28
    const int bk = tid >> 5;         // 0..7
    const int bn = (tid & 31) << 2;  // 0,4,..,124

    for (int kc = 0; kc < 128; kc += 32) {
#pragma unroll
        for (int q = 0; q < 4; q++) {
            int r = ar + q * 32;
            int gr = rowBase + r;
            float4 v = make_float4(0.f, 0.f, 0.f, 0.f);
            if (gr < nrows) v = *(const float4*)(A + (size_t)gr * HIDd + kc + ak);
            As[ak + 0][r] = v.x; As[ak + 1][r] = v.y;
            As[ak + 2][r] = v.z; As[ak + 3][r] = v.w;
        }
#pragma unroll
        for (int q = 0; q < 4; q++) {
            int r = bk + q * 8;
            *(float4*)&Bs[r][bn] = *(const float4*)(W + (size_t)(kc + r) * HIDd + bn);
        }
        __syncthreads();
#pragma unroll
        for (int kk = 0; kk < 32; kk++) {
            float a[8], b[8];
            *(float4*)(a)     = *(const float4*)&As[kk][tm];
            *(float4*)(a + 4) = *(const float4*)&As[kk][tm + 4];
            *(float4*)(b)     = *(const float4*)&Bs[kk][tn];
            *(float4*)(b + 4) = *(const float4*)&Bs[kk][tn + 4];
#pragma unroll
            for (int i = 0; i < 8; i++)
#pragma unroll
                for (int j = 0; j < 8; j++) acc[i][j] = fmaf(a[i], b[j], acc[i][j]);
        }
        __syncthreads();
    }

    float bb[8];
#pragma unroll
    for (int j = 0; j < 8; j++) bb[j] = bias[tn + j];
#pragma unroll
    for (int i = 0; i < 8; i++) {
        int gr = rowBase + tm + i;
        if (gr < nrows) {
            float4 o;
            o.x = acc[i][0] + bb[0]; o.y = acc[i][1] + bb[1];
            o.z = acc[i][2] + bb[2]; o.w = acc[i][3] + bb[3];
            *(float4*)(C + (size_t)gr * HIDd + tn) = o;
            o.x = acc[i][4] + bb[4]; o.y = acc[i][5] + bb[5];
            o.z = acc[i][6] + bb[6]; o.w = acc[i][7] + bb[7];
            *(float4*)(C + (size_t)gr * HIDd + tn + 4) = o;
        }
    }
}

// ---------------- edge pass: one warp per edge ----------------
// logit[e,h] = sum_c att[h,c] * lrelu(xl[src,h,c] + xr[dst,h,c] + (ea16 @ M)[h,c])
// p = exp(logit); num[dst] += p*xl[src]; den[dst,h] += p
__global__ void __launch_bounds__(256) edge_kernel(const int* __restrict__ src,
                                                   const int* __restrict__ dst,
                                                   const float* __restrict__ eattr,
                                                   const float* __restrict__ xl,
                                                   const float* __restrict__ xr,
                                                   const float* __restrict__ M,
                                                   const float* __restrict__ cvec,
                                                   const float* __restrict__ att,
                                                   float* __restrict__ num,
                                                   float* __restrict__ den) {
    __shared__ __align__(16) float sM[EFd * HIDd];
    __shared__ __align__(16) float sC[HIDd];
    __shared__ __align__(16) float sA[HIDd];
    const int tid = threadIdx.x;
    for (int i = tid; i < EFd * HIDd; i += 256) sM[i] = M[i];
    if (tid < HIDd) { sC[tid] = cvec[tid]; sA[tid] = att[tid]; }
    __syncthreads();

    const int e = (blockIdx.x * 256 + tid) >> 5;
    const int lane = tid & 31;
    if (e >= Ee) return;

    const int s = src[e];
    const int d = dst[e];
    float eav = eattr[(size_t)e * EFd + (lane & 15)];

    float4 xlv = ((const float4*)xl)[(size_t)s * 32 + lane];
    float4 xrv = ((const float4*)xr)[(size_t)d * 32 + lane];

    float4 em = ((const float4*)sC)[lane];
    const float4* sM4 = (const float4*)sM;
#pragma unroll
    for (int k = 0; k < EFd; k++) {
        float a = __shfl_sync(0xffffffffu, eav, k);
        float4 mv = sM4[k * 32 + lane];
        em.x = fmaf(a, mv.x, em.x);
        em.y = fmaf(a, mv.y, em.y);
        em.z = fmaf(a, mv.z, em.z);
        em.w = fmaf(a, mv.w, em.w);
    }
    float4 m;
    m.x = xlv.x + xrv.x + em.x;
    m.y = xlv.y + xrv.y + em.y;
    m.z = xlv.z + xrv.z + em.z;
    m.w = xlv.w + xrv.w + em.w;
    m.x = (m.x > 0.f) ? m.x : 0.2f * m.x;
    m.y = (m.y > 0.f) ? m.y : 0.2f * m.y;
    m.z = (m.z > 0.f) ? m.z : 0.2f * m.z;
    m.w = (m.w > 0.f) ? m.w : 0.2f * m.w;

    float4 av = ((const float4*)sA)[lane];
    float part = m.x * av.x + m.y * av.y + m.z * av.z + m.w * av.w;
    part += __shfl_xor_sync(0xffffffffu, part, 1);
    part += __shfl_xor_sync(0xffffffffu, part, 2);  // logit for head = lane>>2

    float p = expf(part);
    if ((lane & 3) == 0) atomicAdd(&den[(size_t)d * Hh + (lane >> 2)], p);

    float4 contrib = make_float4(p * xlv.x, p * xlv.y, p * xlv.z, p * xlv.w);
    atomicAdd(((float4*)num) + (size_t)d * 32 + lane, contrib);  // red.global.v4.f32 (sm_90+)
}

// ---------------- node epilogue: one warp per node ----------------
// out = num/(den+1e-16) + bias_o; LN(g,b); relu; x += out   (in place on x)
__global__ void __launch_bounds__(256) epilogue_kernel(const float* __restrict__ num,
                                                       const float* __restrict__ den,
                                                       const float* __restrict__ bias_o,
                                                       const float* __restrict__ lng,
                                                       const float* __restrict__ lnb,
                                                       float* __restrict__ x) {
    const int n = (blockIdx.x * 256 + threadIdx.x) >> 5;
    const int lane = threadIdx.x & 31;
    if (n >= Nn) return;

    float4 o = ((const float4*)num)[(size_t)n * 32 + lane];
    float inv = 1.0f / (den[(size_t)n * Hh + (lane >> 2)] + 1e-16f);
    float4 bo = ((const float4*)bias_o)[lane];
    o.x = o.x * inv + bo.x;
    o.y = o.y * inv + bo.y;
    o.z = o.z * inv + bo.z;
    o.w = o.w * inv + bo.w;

    float s  = o.x + o.y + o.z + o.w;
    float sq = o.x * o.x + o.y * o.y + o.z * o.z + o.w * o.w;
#pragma unroll
    for (int off = 16; off > 0; off >>= 1) {
        s  += __shfl_xor_sync(0xffffffffu, s, off);
        sq += __shfl_xor_sync(0xffffffffu, sq, off);
    }
    float mu  = s * (1.0f / 128.0f);
    float var = sq * (1.0f / 128.0f) - mu * mu;
    float rstd = rsqrtf(var + 1e-5f);

    float4 gv = ((const float4*)lng)[lane];
    float4 bv = ((const float4*)lnb)[lane];
    float4 xv = ((float4*)x)[(size_t)n * 32 + lane];
    float y;
    y = gv.x * (o.x - mu) * rstd + bv.x; xv.x += fmaxf(y, 0.f);
    y = gv.y * (o.y - mu) * rstd + bv.y; xv.y += fmaxf(y, 0.f);
    y = gv.z * (o.z - mu) * rstd + bv.z; xv.z += fmaxf(y, 0.f);
    y = gv.w * (o.w - mu) * rstd + bv.w; xv.w += fmaxf(y, 0.f);
    ((float4*)x)[(size_t)n * 32 + lane] = xv;
}

// ---------------- launch ----------------
extern "C" void kernel_launch(void* const* d_in, const int* in_sizes, int n_in,
                              void* d_out, int out_size) {
    const float* x   = (const float*)d_in[0];
    const int*   ei  = (const int*)d_in[2];
    const float* ea  = (const float*)d_in[3];
    const float* Wt  = (const float*)d_in[4];
    const float* bt  = (const float*)d_in[5];
    const float* Wl  = (const float*)d_in[6];
    const float* bl  = (const float*)d_in[7];
    const float* Wr  = (const float*)d_in[8];
    const float* br  = (const float*)d_in[9];
    const float* We  = (const float*)d_in[10];
    const float* att = (const float*)d_in[11];
    const float* bo  = (const float*)d_in[12];
    const float* lg  = (const float*)d_in[13];
    const float* lb  = (const float*)d_in[14];
    float* xbuf = (float*)d_out;

    float *pxl, *pxr, *pnum, *pden, *pM, *pc;
    cudaGetSymbolAddress((void**)&pxl,  g_xl);
    cudaGetSymbolAddress((void**)&pxr,  g_xr);
    cudaGetSymbolAddress((void**)&pnum, g_num);
    cudaGetSymbolAddress((void**)&pden, g_den);
    cudaGetSymbolAddress((void**)&pM,   g_M);
    cudaGetSymbolAddress((void**)&pc,   g_c);

    const int n4x = Nn * 32;
    copy_kernel<<<(n4x + 255) / 256, 256>>>((const float4*)x, (float4*)xbuf, n4x);
    precompute_kernel<<<Ll, HIDd>>>(Wt, bt, We, pM, pc);

    for (int l = 0; l < Ll; l++) {
        gemm128<<<(Nn + 127) / 128, 256>>>(xbuf, Wl + (size_t)l * HIDd * HIDd, bl + l * HIDd, pxl, Nn);
        gemm128<<<(Nn + 127) / 128, 256>>>(xbuf, Wr + (size_t)l * HIDd * HIDd, br + l * HIDd, pxr, Nn);
        zero_kernel<<<(n4x + 255) / 256, 256>>>((float4*)pnum, (float4*)pden, n4x, Nn * 2);
        edge_kernel<<<Ee / 8, 256>>>(ei, ei + Ee, ea, pxl, pxr,
                                     pM + (size_t)l * EFd * HIDd, pc + l * HIDd,
                                     att + l * HIDd, pnum, pden);
        epilogue_kernel<<<(n4x + 255) / 256, 256>>>(pnum, pden, bo + l * HIDd,
                                                    lg + l * HIDd, lb + l * HIDd, xbuf);
    }
}

// round 3
// speedup vs baseline: 1.1132x; 1.1132x over previous
#include <cuda_runtime.h>
#include <cuda_bf16.h>

#define Nn  50000
#define Ee  640000
#define HIDd 128
#define Hh  8
#define Cc  16
#define EFd 16
#define Ll  3

// ---------------- scratch (static device globals; no allocations) ----------------
__device__ __align__(16) float g_xl[Nn * HIDd];
__device__ __align__(16) float g_xr[Nn * HIDd];
__device__ __align__(16) float g_M[Ll * EFd * HIDd];
__device__ __align__(16) float g_c[Ll * HIDd];
__device__ int g_deg[Nn];
__device__ int g_off[Nn + 1];
__device__ int g_cur[Nn];
__device__ int g_eid[Ee];

// ---------------- small utility kernels ----------------
__global__ void copy_kernel(const float4* __restrict__ src, float4* __restrict__ dst, int n4) {
    int i = blockIdx.x * blockDim.x + threadIdx.x;
    if (i < n4) dst[i] = src[i];
}

__global__ void zero_deg_kernel(int* __restrict__ deg) {
    int i = blockIdx.x * blockDim.x + threadIdx.x;
    if (i < Nn) deg[i] = 0;
}

__global__ void hist_kernel(const int* __restrict__ dst, int* __restrict__ deg) {
    int e = blockIdx.x * blockDim.x + threadIdx.x;
    if (e < Ee) atomicAdd(&deg[dst[e]], 1);
}

// single-block exclusive scan over deg -> off, cur ; off[Nn] = Ee
__global__ void scan_kernel(const int* __restrict__ deg, int* __restrict__ off,
                            int* __restrict__ cur) {
    __shared__ int sums[1024];
    const int t = threadIdx.x;
    const int CH = 49;  // 1024*49 = 50176 >= Nn
    int beg = t * CH;
    int local = 0;
#pragma unroll 1
    for (int i = 0; i < CH; i++) {
        int idx = beg + i;
        if (idx < Nn) local += deg[idx];
    }
    sums[t] = local;
    __syncthreads();
    int run = local;
    for (int ofs = 1; ofs < 1024; ofs <<= 1) {
        int u = (t >= ofs) ? sums[t - ofs] : 0;
        __syncthreads();
        run += u;
        sums[t] = run;
        __syncthreads();
    }
    int base = run - local;  // exclusive prefix
#pragma unroll 1
    for (int i = 0; i < CH; i++) {
        int idx = beg + i;
        if (idx < Nn) {
            off[idx] = base;
            cur[idx] = base;
            base += deg[idx];
        }
    }
    if (t == 0) off[Nn] = Ee;
}

__global__ void scatter_kernel(const int* __restrict__ dst, int* __restrict__ cur,
                               int* __restrict__ eid) {
    int e = blockIdx.x * blockDim.x + threadIdx.x;
    if (e < Ee) {
        int p = atomicAdd(&cur[dst[e]], 1);
        eid[p] = e;
    }
}

// M[l] = Wt(16x128) @ We[l](128x128); c[l] = bt @ We[l]
__global__ void precompute_kernel(const float* __restrict__ Wt, const float* __restrict__ bt,
                                  const float* __restrict__ We,
                                  float* __restrict__ M, float* __restrict__ cv) {
    int l = blockIdx.x;
    int j = threadIdx.x;  // 0..127
    const float* Wel = We + l * HIDd * HIDd;
    float acc[EFd];
#pragma unroll
    for (int k = 0; k < EFd; k++) acc[k] = 0.f;
    float cacc = 0.f;
    for (int i = 0; i < HIDd; i++) {
        float w = Wel[i * HIDd + j];
        cacc = fmaf(bt[i], w, cacc);
#pragma unroll
        for (int k = 0; k < EFd; k++) acc[k] = fmaf(Wt[k * HIDd + i], w, acc[k]);
    }
#pragma unroll
    for (int k = 0; k < EFd; k++) M[l * EFd * HIDd + k * HIDd + j] = acc[k];
    cv[l * HIDd + j] = cacc;
}

// ---------------- SGEMM: C[nrows,128] = A[nrows,128] @ W[128,128] + bias ----------------
// blockIdx.y selects (W0,b0,C0) vs (W1,b1,C1) so xl/xr run in one launch.
__global__ void __launch_bounds__(256, 2) gemm128x2(const float* __restrict__ A,
                                                    const float* __restrict__ W0,
                                                    const float* __restrict__ b0,
                                                    float* __restrict__ C0,
                                                    const float* __restrict__ W1,
                                                    const float* __restrict__ b1,
                                                    float* __restrict__ C1,
                                                    int nrows) {
    const float* W    = blockIdx.y ? W1 : W0;
    const float* bias = blockIdx.y ? b1 : b0;
    float*       C    = blockIdx.y ? C1 : C0;

    __shared__ __align__(16) float As[32][132];
    __shared__ __align__(16) float Bs[32][128];
    const int tid = threadIdx.x;
    const int tn = (tid & 15) * 8;
    const int tm = (tid >> 4) * 8;
    const int rowBase = blockIdx.x * 128;

    float acc[8][8];
#pragma unroll
    for (int i = 0; i < 8; i++)
#pragma unroll
        for (int j = 0; j < 8; j++) acc[i][j] = 0.f;

    const int ar = tid >> 3;
    const int ak = (tid & 7) << 2;
    const int bk = tid >> 5;
    const int bn = (tid & 31) << 2;

    for (int kc = 0; kc < 128; kc += 32) {
#pragma unroll
        for (int q = 0; q < 4; q++) {
            int r = ar + q * 32;
            int gr = rowBase + r;
            float4 v = make_float4(0.f, 0.f, 0.f, 0.f);
            if (gr < nrows) v = *(const float4*)(A + (size_t)gr * HIDd + kc + ak);
            As[ak + 0][r] = v.x; As[ak + 1][r] = v.y;
            As[ak + 2][r] = v.z; As[ak + 3][r] = v.w;
        }
#pragma unroll
        for (int q = 0; q < 4; q++) {
            int r = bk + q * 8;
            *(float4*)&Bs[r][bn] = *(const float4*)(W + (size_t)(kc + r) * HIDd + bn);
        }
        __syncthreads();
#pragma unroll
        for (int kk = 0; kk < 32; kk++) {
            float a[8], b[8];
            *(float4*)(a)     = *(const float4*)&As[kk][tm];
            *(float4*)(a + 4) = *(const float4*)&As[kk][tm + 4];
            *(float4*)(b)     = *(const float4*)&Bs[kk][tn];
            *(float4*)(b + 4) = *(const float4*)&Bs[kk][tn + 4];
#pragma unroll
            for (int i = 0; i < 8; i++)
#pragma unroll
                for (int j = 0; j < 8; j++) acc[i][j] = fmaf(a[i], b[j], acc[i][j]);
        }
        __syncthreads();
    }

    float bb[8];
#pragma unroll
    for (int j = 0; j < 8; j++) bb[j] = bias[tn + j];
#pragma unroll
    for (int i = 0; i < 8; i++) {
        int gr = rowBase + tm + i;
        if (gr < nrows) {
            float4 o;
            o.x = acc[i][0] + bb[0]; o.y = acc[i][1] + bb[1];
            o.z = acc[i][2] + bb[2]; o.w = acc[i][3] + bb[3];
            *(float4*)(C + (size_t)gr * HIDd + tn) = o;
            o.x = acc[i][4] + bb[4]; o.y = acc[i][5] + bb[5];
            o.z = acc[i][6] + bb[6]; o.w = acc[i][7] + bb[7];
            *(float4*)(C + (size_t)gr * HIDd + tn + 4) = o;
        }
    }
}

// ---------------- fused node pass: one warp per dst node ----------------
__global__ void __launch_bounds__(256) node_kernel(const int* __restrict__ srcArr,
                                                   const float* __restrict__ eattr,
                                                   const float* __restrict__ xl,
                                                   const float* __restrict__ xr,
                                                   const int* __restrict__ off,
                                                   const int* __restrict__ eid,
                                                   const float* __restrict__ M,
                                                   const float* __restrict__ cvec,
                                                   const float* __restrict__ att,
                                                   const float* __restrict__ bias_o,
                                                   const float* __restrict__ lng,
                                                   const float* __restrict__ lnb,
                                                   float* __restrict__ x) {
    __shared__ __align__(16) float sM[EFd * HIDd];
    __shared__ __align__(16) float sC[HIDd];
    __shared__ __align__(16) float sA[HIDd];
    const int tid = threadIdx.x;
    for (int i = tid; i < EFd * HIDd; i += 256) sM[i] = M[i];
    if (tid < HIDd) { sC[tid] = cvec[tid]; sA[tid] = att[tid]; }
    __syncthreads();

    const int n = (blockIdx.x * 256 + tid) >> 5;
    const int lane = tid & 31;
    if (n >= Nn) return;

    const int beg = off[n];
    const int end = off[n + 1];

    const float4 xrv = ((const float4*)xr)[(size_t)n * 32 + lane];
    const float4 cv4 = ((const float4*)sC)[lane];
    const float4 av  = ((const float4*)sA)[lane];
    const float4* sM4 = (const float4*)sM;

    float4 acc = make_float4(0.f, 0.f, 0.f, 0.f);
    float dsum = 0.f;

    // 1-deep prefetch of the (eid, src) index chain to overlap dependent-load latency
    int e_next = (beg < end) ? eid[beg] : 0;
    int s_next = (beg < end) ? srcArr[e_next] : 0;

    for (int i = beg; i < end; i++) {
        const int e = e_next;
        const int s = s_next;
        if (i + 1 < end) {
            e_next = eid[i + 1];
            s_next = srcArr[e_next];
        }
        float eav = eattr[(size_t)e * EFd + (lane & 15)];
        float4 xlv = ((const float4*)xl)[(size_t)s * 32 + lane];

        float4 em = cv4;
#pragma unroll
        for (int k = 0; k < EFd; k++) {
            float a = __shfl_sync(0xffffffffu, eav, k);
            float4 mv = sM4[k * 32 + lane];
            em.x = fmaf(a, mv.x, em.x);
            em.y = fmaf(a, mv.y, em.y);
            em.z = fmaf(a, mv.z, em.z);
            em.w = fmaf(a, mv.w, em.w);
        }
        float4 m;
        m.x = xlv.x + xrv.x + em.x;
        m.y = xlv.y + xrv.y + em.y;
        m.z = xlv.z + xrv.z + em.z;
        m.w = xlv.w + xrv.w + em.w;
        m.x = (m.x > 0.f) ? m.x : 0.2f * m.x;
        m.y = (m.y > 0.f) ? m.y : 0.2f * m.y;
        m.z = (m.z > 0.f) ? m.z : 0.2f * m.z;
        m.w = (m.w > 0.f) ? m.w : 0.2f * m.w;

        float part = m.x * av.x + m.y * av.y + m.z * av.z + m.w * av.w;
        part += __shfl_xor_sync(0xffffffffu, part, 1);
        part += __shfl_xor_sync(0xffffffffu, part, 2);  // logit of head = lane>>2

        float p = expf(part);
        dsum += p;
        acc.x = fmaf(p, xlv.x, acc.x);
        acc.y = fmaf(p, xlv.y, acc.y);
        acc.z = fmaf(p, xlv.z, acc.z);
        acc.w = fmaf(p, xlv.w, acc.w);
    }

    const float inv = 1.0f / (dsum + 1e-16f);
    float4 bo = ((const float4*)bias_o)[lane];
    float4 o;
    o.x = acc.x * inv + bo.x;
    o.y = acc.y * inv + bo.y;
    o.z = acc.z * inv + bo.z;
    o.w = acc.w * inv + bo.w;

    float s  = o.x + o.y + o.z + o.w;
    float sq = o.x * o.x + o.y * o.y + o.z * o.z + o.w * o.w;
#pragma unroll
    for (int ofs = 16; ofs > 0; ofs >>= 1) {
        s  += __shfl_xor_sync(0xffffffffu, s, ofs);
        sq += __shfl_xor_sync(0xffffffffu, sq, ofs);
    }
    float mu   = s * (1.0f / 128.0f);
    float var  = sq * (1.0f / 128.0f) - mu * mu;
    float rstd = rsqrtf(var + 1e-5f);

    float4 gv = ((const float4*)lng)[lane];
    float4 bv = ((const float4*)lnb)[lane];
    float4 xv = ((float4*)x)[(size_t)n * 32 + lane];
    float y;
    y = gv.x * (o.x - mu) * rstd + bv.x; xv.x += fmaxf(y, 0.f);
    y = gv.y * (o.y - mu) * rstd + bv.y; xv.y += fmaxf(y, 0.f);
    y = gv.z * (o.z - mu) * rstd + bv.z; xv.z += fmaxf(y, 0.f);
    y = gv.w * (o.w - mu) * rstd + bv.w; xv.w += fmaxf(y, 0.f);
    ((float4*)x)[(size_t)n * 32 + lane] = xv;
}

// ---------------- launch ----------------
extern "C" void kernel_launch(void* const* d_in, const int* in_sizes, int n_in,
                              void* d_out, int out_size) {
    const float* x   = (const float*)d_in[0];
    const int*   ei  = (const int*)d_in[2];
    const float* ea  = (const float*)d_in[3];
    const float* Wt  = (const float*)d_in[4];
    const float* bt  = (const float*)d_in[5];
    const float* Wl  = (const float*)d_in[6];
    const float* bl  = (const float*)d_in[7];
    const float* Wr  = (const float*)d_in[8];
    const float* br  = (const float*)d_in[9];
    const float* We  = (const float*)d_in[10];
    const float* att = (const float*)d_in[11];
    const float* bo  = (const float*)d_in[12];
    const float* lg  = (const float*)d_in[13];
    const float* lb  = (const float*)d_in[14];
    float* xbuf = (float*)d_out;

    float *pxl, *pxr, *pM, *pc;
    int *pdeg, *poff, *pcur, *peid;
    cudaGetSymbolAddress((void**)&pxl,  g_xl);
    cudaGetSymbolAddress((void**)&pxr,  g_xr);
    cudaGetSymbolAddress((void**)&pM,   g_M);
    cudaGetSymbolAddress((void**)&pc,   g_c);
    cudaGetSymbolAddress((void**)&pdeg, g_deg);
    cudaGetSymbolAddress((void**)&poff, g_off);
    cudaGetSymbolAddress((void**)&pcur, g_cur);
    cudaGetSymbolAddress((void**)&peid, g_eid);

    const int* srcArr = ei;
    const int* dstArr = ei + Ee;
    const int n4x = Nn * 32;

    copy_kernel<<<(n4x + 255) / 256, 256>>>((const float4*)x, (float4*)xbuf, n4x);
    precompute_kernel<<<Ll, HIDd>>>(Wt, bt, We, pM, pc);

    // CSR build (once per launch; shared by all 3 layers)
    zero_deg_kernel<<<(Nn + 255) / 256, 256>>>(pdeg);
    hist_kernel<<<(Ee + 255) / 256, 256>>>(dstArr, pdeg);
    scan_kernel<<<1, 1024>>>(pdeg, poff, pcur);
    scatter_kernel<<<(Ee + 255) / 256, 256>>>(dstArr, pcur, peid);

    dim3 ggrid((Nn + 127) / 128, 2);
    for (int l = 0; l < Ll; l++) {
        gemm128x2<<<ggrid, 256>>>(xbuf,
                                  Wl + (size_t)l * HIDd * HIDd, bl + l * HIDd, pxl,
                                  Wr + (size_t)l * HIDd * HIDd, br + l * HIDd, pxr, Nn);
        node_kernel<<<(Nn * 32 + 255) / 256, 256>>>(srcArr, ea, pxl, pxr, poff, peid,
                                                    pM + (size_t)l * EFd * HIDd, pc + l * HIDd,
                                                    att + l * HIDd, bo + l * HIDd,
                                                    lg + l * HIDd, lb + l * HIDd, xbuf);
    }
}

// round 4
// speedup vs baseline: 1.1343x; 1.0189x over previous
#include <cuda_runtime.h>
#include <cuda_bf16.h>

#define Nn  50000
#define Ee  640000
#define HIDd 128
#define Hh  8
#define Cc  16
#define EFd 16
#define Ll  3

// ---------------- scratch (static device globals; no allocations) ----------------
__device__ __align__(16) float g_xl[Nn * HIDd];
__device__ __align__(16) float g_xr[Nn * HIDd];
__device__ __align__(16) float g_M[Ll * EFd * HIDd];
__device__ __align__(16) float g_c[Ll * HIDd];
__device__ int g_deg[Nn];
__device__ int g_off[Nn + 1];
__device__ int g_cur[Nn];
__device__ int g_eid[Ee];
__device__ int g_srcS[Ee];                       // src reordered into CSR order
__device__ __align__(16) float g_eaS[Ee * EFd];  // edge_attr reordered into CSR order

// ---------------- small utility kernels ----------------
__global__ void copy_kernel(const float4* __restrict__ src, float4* __restrict__ dst, int n4) {
    int i = blockIdx.x * blockDim.x + threadIdx.x;
    if (i < n4) dst[i] = src[i];
}

__global__ void zero_deg_kernel(int* __restrict__ deg) {
    int i = blockIdx.x * blockDim.x + threadIdx.x;
    if (i < Nn) deg[i] = 0;
}

__global__ void hist_kernel(const int* __restrict__ dst, int* __restrict__ deg) {
    int e = blockIdx.x * blockDim.x + threadIdx.x;
    if (e < Ee) atomicAdd(&deg[dst[e]], 1);
}

// single-block exclusive scan over deg -> off, cur ; off[Nn] = Ee
__global__ void scan_kernel(const int* __restrict__ deg, int* __restrict__ off,
                            int* __restrict__ cur) {
    __shared__ int sums[1024];
    const int t = threadIdx.x;
    const int CH = 49;
    int beg = t * CH;
    int local = 0;
#pragma unroll 1
    for (int i = 0; i < CH; i++) {
        int idx = beg + i;
        if (idx < Nn) local += deg[idx];
    }
    sums[t] = local;
    __syncthreads();
    int run = local;
    for (int ofs = 1; ofs < 1024; ofs <<= 1) {
        int u = (t >= ofs) ? sums[t - ofs] : 0;
        __syncthreads();
        run += u;
        sums[t] = run;
        __syncthreads();
    }
    int base = run - local;
#pragma unroll 1
    for (int i = 0; i < CH; i++) {
        int idx = beg + i;
        if (idx < Nn) {
            off[idx] = base;
            cur[idx] = base;
            base += deg[idx];
        }
    }
    if (t == 0) off[Nn] = Ee;
}

__global__ void scatter_kernel(const int* __restrict__ dst, int* __restrict__ cur,
                               int* __restrict__ eid) {
    int e = blockIdx.x * blockDim.x + threadIdx.x;
    if (e < Ee) {
        int p = atomicAdd(&cur[dst[e]], 1);
        eid[p] = e;
    }
}

// permute (src, edge_attr) into CSR slot order: sequential reads in node pass
__global__ void reorder_kernel(const int* __restrict__ eid, const int* __restrict__ srcArr,
                               const float* __restrict__ ea,
                               int* __restrict__ srcS, float* __restrict__ eaS) {
    int i = blockIdx.x * blockDim.x + threadIdx.x;
    if (i >= Ee) return;
    int e = eid[i];
    srcS[i] = srcArr[e];
    const float4* s4 = (const float4*)(ea + (size_t)e * EFd);
    float4* d4 = (float4*)(eaS + (size_t)i * EFd);
    d4[0] = s4[0]; d4[1] = s4[1]; d4[2] = s4[2]; d4[3] = s4[3];
}

// M[l] = Wt(16x128) @ We[l](128x128); c[l] = bt @ We[l]
__global__ void precompute_kernel(const float* __restrict__ Wt, const float* __restrict__ bt,
                                  const float* __restrict__ We,
                                  float* __restrict__ M, float* __restrict__ cv) {
    int l = blockIdx.x;
    int j = threadIdx.x;
    const float* Wel = We + l * HIDd * HIDd;
    float acc[EFd];
#pragma unroll
    for (int k = 0; k < EFd; k++) acc[k] = 0.f;
    float cacc = 0.f;
    for (int i = 0; i < HIDd; i++) {
        float w = Wel[i * HIDd + j];
        cacc = fmaf(bt[i], w, cacc);
#pragma unroll
        for (int k = 0; k < EFd; k++) acc[k] = fmaf(Wt[k * HIDd + i], w, acc[k]);
    }
#pragma unroll
    for (int k = 0; k < EFd; k++) M[l * EFd * HIDd + k * HIDd + j] = acc[k];
    cv[l * HIDd + j] = cacc;
}

// ---------------- SGEMM: C[nrows,128] = A[nrows,128] @ W[128,128] + bias ----------------
__global__ void __launch_bounds__(256, 2) gemm128x2(const float* __restrict__ A,
                                                    const float* __restrict__ W0,
                                                    const float* __restrict__ b0,
                                                    float* __restrict__ C0,
                                                    const float* __restrict__ W1,
                                                    const float* __restrict__ b1,
                                                    float* __restrict__ C1,
                                                    int nrows) {
    const float* W    = blockIdx.y ? W1 : W0;
    const float* bias = blockIdx.y ? b1 : b0;
    float*       C    = blockIdx.y ? C1 : C0;

    __shared__ __align__(16) float As[32][132];
    __shared__ __align__(16) float Bs[32][128];
    const int tid = threadIdx.x;
    const int tn = (tid & 15) * 8;
    const int tm = (tid >> 4) * 8;
    const int rowBase = blockIdx.x * 128;

    float acc[8][8];
#pragma unroll
    for (int i = 0; i < 8; i++)
#pragma unroll
        for (int j = 0; j < 8; j++) acc[i][j] = 0.f;

    const int ar = tid >> 3;
    const int ak = (tid & 7) << 2;
    const int bk = tid >> 5;
    const int bn = (tid & 31) << 2;

    for (int kc = 0; kc < 128; kc += 32) {
#pragma unroll
        for (int q = 0; q < 4; q++) {
            int r = ar + q * 32;
            int gr = rowBase + r;
            float4 v = make_float4(0.f, 0.f, 0.f, 0.f);
            if (gr < nrows) v = *(const float4*)(A + (size_t)gr * HIDd + kc + ak);
            As[ak + 0][r] = v.x; As[ak + 1][r] = v.y;
            As[ak + 2][r] = v.z; As[ak + 3][r] = v.w;
        }
#pragma unroll
        for (int q = 0; q < 4; q++) {
            int r = bk + q * 8;
            *(float4*)&Bs[r][bn] = *(const float4*)(W + (size_t)(kc + r) * HIDd + bn);
        }
        __syncthreads();
#pragma unroll
        for (int kk = 0; kk < 32; kk++) {
            float a[8], b[8];
            *(float4*)(a)     = *(const float4*)&As[kk][tm];
            *(float4*)(a + 4) = *(const float4*)&As[kk][tm + 4];
            *(float4*)(b)     = *(const float4*)&Bs[kk][tn];
            *(float4*)(b + 4) = *(const float4*)&Bs[kk][tn + 4];
#pragma unroll
            for (int i = 0; i < 8; i++)
#pragma unroll
                for (int j = 0; j < 8; j++) acc[i][j] = fmaf(a[i], b[j], acc[i][j]);
        }
        __syncthreads();
    }

    float bb[8];
#pragma unroll
    for (int j = 0; j < 8; j++) bb[j] = bias[tn + j];
#pragma unroll
    for (int i = 0; i < 8; i++) {
        int gr = rowBase + tm + i;
        if (gr < nrows) {
            float4 o;
            o.x = acc[i][0] + bb[0]; o.y = acc[i][1] + bb[1];
            o.z = acc[i][2] + bb[2]; o.w = acc[i][3] + bb[3];
            *(float4*)(C + (size_t)gr * HIDd + tn) = o;
            o.x = acc[i][4] + bb[4]; o.y = acc[i][5] + bb[5];
            o.z = acc[i][6] + bb[6]; o.w = acc[i][7] + bb[7];
            *(float4*)(C + (size_t)gr * HIDd + tn + 4) = o;
        }
    }
}

// ---------------- fused node pass: one warp per dst node ----------------
// Software-pipelined: src/eattr/xl data loaded one iteration ahead;
// sequential srcS/eaS reads (CSR-ordered); exp via exp2 with pre-scaled att.
__global__ void __launch_bounds__(256) node_kernel(const float* __restrict__ eaS,
                                                   const int* __restrict__ srcS,
                                                   const float* __restrict__ xl,
                                                   const float* __restrict__ xr,
                                                   const int* __restrict__ off,
                                                   const float* __restrict__ M,
                                                   const float* __restrict__ cvec,
                                                   const float* __restrict__ att,
                                                   const float* __restrict__ bias_o,
                                                   const float* __restrict__ lng,
                                                   const float* __restrict__ lnb,
                                                   float* __restrict__ x) {
    __shared__ __align__(16) float sM[EFd * HIDd];
    __shared__ __align__(16) float sC[HIDd];
    __shared__ __align__(16) float sA[HIDd];
    const int tid = threadIdx.x;
    for (int i = tid; i < EFd * HIDd; i += 256) sM[i] = M[i];
    if (tid < HIDd) {
        sC[tid] = cvec[tid];
        sA[tid] = att[tid] * 1.4426950408889634f;  // fold log2(e): exp(x)=exp2(x*log2e)
    }
    __syncthreads();

    const int n = (blockIdx.x * 256 + tid) >> 5;
    const int lane = tid & 31;
    if (n >= Nn) return;

    const int beg = off[n];
    const int end = off[n + 1];

    const float4 xrv = ((const float4*)xr)[(size_t)n * 32 + lane];
    const float4 cv4 = ((const float4*)sC)[lane];
    const float4 av  = ((const float4*)sA)[lane];
    const float4* sM4 = (const float4*)sM;

    float4 acc = make_float4(0.f, 0.f, 0.f, 0.f);
    float dsum = 0.f;

    // pipeline registers (data for iteration i resident before loop body i)
    float  eav0 = 0.f;
    float4 xlv0 = make_float4(0.f, 0.f, 0.f, 0.f);
    if (beg < end) {
        eav0 = eaS[(size_t)beg * EFd + (lane & 15)];
        int s0 = srcS[beg];
        xlv0 = ((const float4*)xl)[(size_t)s0 * 32 + lane];
    }

    for (int i = beg; i < end; i++) {
        // prefetch next iteration's data (sequential eaS/srcS; gathered xl)
        float  eav1 = eav0;
        float4 xlv1 = xlv0;
        if (i + 1 < end) {
            eav1 = eaS[(size_t)(i + 1) * EFd + (lane & 15)];
            int s1 = srcS[i + 1];
            xlv1 = ((const float4*)xl)[(size_t)s1 * 32 + lane];
        }

        const float  eav = eav0;
        const float4 xlv = xlv0;

        // em = c + ea(16) @ M(16x128), two independent 8-deep chains
        float4 emA = cv4;
        float4 emB = make_float4(0.f, 0.f, 0.f, 0.f);
#pragma unroll
        for (int k = 0; k < 8; k++) {
            float a = __shfl_sync(0xffffffffu, eav, k);
            float4 mv = sM4[k * 32 + lane];
            emA.x = fmaf(a, mv.x, emA.x);
            emA.y = fmaf(a, mv.y, emA.y);
            emA.z = fmaf(a, mv.z, emA.z);
            emA.w = fmaf(a, mv.w, emA.w);
        }
#pragma unroll
        for (int k = 8; k < 16; k++) {
            float a = __shfl_sync(0xffffffffu, eav, k);
            float4 mv = sM4[k * 32 + lane];
            emB.x = fmaf(a, mv.x, emB.x);
            emB.y = fmaf(a, mv.y, emB.y);
            emB.z = fmaf(a, mv.z, emB.z);
            emB.w = fmaf(a, mv.w, emB.w);
        }
        float4 m;
        m.x = xlv.x + xrv.x + emA.x + emB.x;
        m.y = xlv.y + xrv.y + emA.y + emB.y;
        m.z = xlv.z + xrv.z + emA.z + emB.z;
        m.w = xlv.w + xrv.w + emA.w + emB.w;
        m.x = (m.x > 0.f) ? m.x : 0.2f * m.x;
        m.y = (m.y > 0.f) ? m.y : 0.2f * m.y;
        m.z = (m.z > 0.f) ? m.z : 0.2f * m.z;
        m.w = (m.w > 0.f) ? m.w : 0.2f * m.w;

        float part = m.x * av.x + m.y * av.y + m.z * av.z + m.w * av.w;
        part += __shfl_xor_sync(0xffffffffu, part, 1);
        part += __shfl_xor_sync(0xffffffffu, part, 2);  // logit*log2e for head lane>>2

        float p = exp2f(part);
        dsum += p;
        acc.x = fmaf(p, xlv.x, acc.x);
        acc.y = fmaf(p, xlv.y, acc.y);
        acc.z = fmaf(p, xlv.z, acc.z);
        acc.w = fmaf(p, xlv.w, acc.w);

        eav0 = eav1;
        xlv0 = xlv1;
    }

    const float inv = 1.0f / (dsum + 1e-16f);
    float4 bo = ((const float4*)bias_o)[lane];
    float4 o;
    o.x = acc.x * inv + bo.x;
    o.y = acc.y * inv + bo.y;
    o.z = acc.z * inv + bo.z;
    o.w = acc.w * inv + bo.w;

    float s  = o.x + o.y + o.z + o.w;
    float sq = o.x * o.x + o.y * o.y + o.z * o.z + o.w * o.w;
#pragma unroll
    for (int ofs = 16; ofs > 0; ofs >>= 1) {
        s  += __shfl_xor_sync(0xffffffffu, s, ofs);
        sq += __shfl_xor_sync(0xffffffffu, sq, ofs);
    }
    float mu   = s * (1.0f / 128.0f);
    float var  = sq * (1.0f / 128.0f) - mu * mu;
    float rstd = rsqrtf(var + 1e-5f);

    float4 gv = ((const float4*)lng)[lane];
    float4 bv = ((const float4*)lnb)[lane];
    float4 xv = ((float4*)x)[(size_t)n * 32 + lane];
    float y;
    y = gv.x * (o.x - mu) * rstd + bv.x; xv.x += fmaxf(y, 0.f);
    y = gv.y * (o.y - mu) * rstd + bv.y; xv.y += fmaxf(y, 0.f);
    y = gv.z * (o.z - mu) * rstd + bv.z; xv.z += fmaxf(y, 0.f);
    y = gv.w * (o.w - mu) * rstd + bv.w; xv.w += fmaxf(y, 0.f);
    ((float4*)x)[(size_t)n * 32 + lane] = xv;
}

// ---------------- launch ----------------
extern "C" void kernel_launch(void* const* d_in, const int* in_sizes, int n_in,
                              void* d_out, int out_size) {
    const float* x   = (const float*)d_in[0];
    const int*   ei  = (const int*)d_in[2];
    const float* ea  = (const float*)d_in[3];
    const float* Wt  = (const float*)d_in[4];
    const float* bt  = (const float*)d_in[5];
    const float* Wl  = (const float*)d_in[6];
    const float* bl  = (const float*)d_in[7];
    const float* Wr  = (const float*)d_in[8];
    const float* br  = (const float*)d_in[9];
    const float* We  = (const float*)d_in[10];
    const float* att = (const float*)d_in[11];
    const float* bo  = (const float*)d_in[12];
    const float* lg  = (const float*)d_in[13];
    const float* lb  = (const float*)d_in[14];
    float* xbuf = (float*)d_out;

    float *pxl, *pxr, *pM, *pc, *peaS;
    int *pdeg, *poff, *pcur, *peid, *psrcS;
    cudaGetSymbolAddress((void**)&pxl,   g_xl);
    cudaGetSymbolAddress((void**)&pxr,   g_xr);
    cudaGetSymbolAddress((void**)&pM,    g_M);
    cudaGetSymbolAddress((void**)&pc,    g_c);
    cudaGetSymbolAddress((void**)&pdeg,  g_deg);
    cudaGetSymbolAddress((void**)&poff,  g_off);
    cudaGetSymbolAddress((void**)&pcur,  g_cur);
    cudaGetSymbolAddress((void**)&peid,  g_eid);
    cudaGetSymbolAddress((void**)&psrcS, g_srcS);
    cudaGetSymbolAddress((void**)&peaS,  g_eaS);

    const int* srcArr = ei;
    const int* dstArr = ei + Ee;
    const int n4x = Nn * 32;

    copy_kernel<<<(n4x + 255) / 256, 256>>>((const float4*)x, (float4*)xbuf, n4x);
    precompute_kernel<<<Ll, HIDd>>>(Wt, bt, We, pM, pc);

    // CSR build + payload permutation (once per launch)
    zero_deg_kernel<<<(Nn + 255) / 256, 256>>>(pdeg);
    hist_kernel<<<(Ee + 255) / 256, 256>>>(dstArr, pdeg);
    scan_kernel<<<1, 1024>>>(pdeg, poff, pcur);
    scatter_kernel<<<(Ee + 255) / 256, 256>>>(dstArr, pcur, peid);
    reorder_kernel<<<(Ee + 255) / 256, 256>>>(peid, srcArr, ea, psrcS, peaS);

    dim3 ggrid((Nn + 127) / 128, 2);
    for (int l = 0; l < Ll; l++) {
        gemm128x2<<<ggrid, 256>>>(xbuf,
                                  Wl + (size_t)l * HIDd * HIDd, bl + l * HIDd, pxl,
                                  Wr + (size_t)l * HIDd * HIDd, br + l * HIDd, pxr, Nn);
        node_kernel<<<(Nn * 32 + 255) / 256, 256>>>(peaS, psrcS, pxl, pxr, poff,
                                                    pM + (size_t)l * EFd * HIDd, pc + l * HIDd,
                                                    att + l * HIDd, bo + l * HIDd,
                                                    lg + l * HIDd, lb + l * HIDd, xbuf);
    }
}